// round 2
// baseline (speedup 1.0000x reference)
#include <cuda_runtime.h>

// RWKV WKV: per-channel affine linear recurrence along T.
//   a_t = d_t * a_{t-1} + ek_t * v_t
//   b_t = d_t * b_{t-1} + ek_t
//   out = sigmoid(r) * a / (b + eps),  d = exp(-exp(w)), ek = exp(k)
//
// 3-pass chunked scan: (1) per-chunk affine composition, (2) per-channel
// exclusive scan over chunk summaries, (3) re-stream with carry-in + output.

#define NB 8
#define NT 4096
#define NC 1024
#define NC4 (NC / 4)          // 256 float4 lanes per row
#define NCHUNK 128            // chunks along T
#define CLEN (NT / NCHUNK)    // 32 timesteps per chunk
#define WKV_EPS 1e-6f

// Scratch: chunk summaries, layout [chunk][b][c] (coalesced for all passes).
__device__ float g_D[NCHUNK * NB * NC];   // decay product per chunk
__device__ float g_A[NCHUNK * NB * NC];   // numerator aggregate / excl. prefix
__device__ float g_B[NCHUNK * NB * NC];   // denominator aggregate / excl. prefix

__device__ __forceinline__ void wkv_acc(float wv, float kv, float vv,
                                        float& a, float& b, float& D) {
    float d  = __expf(-__expf(wv));
    float ek = __expf(kv);
    a = fmaf(a, d, ek * vv);
    b = fmaf(b, d, ek);
    D *= d;
}

__device__ __forceinline__ float wkv_emit(float rv, float wv, float kv, float vv,
                                          float& a, float& b) {
    float d  = __expf(-__expf(wv));
    float ek = __expf(kv);
    a = fmaf(a, d, ek * vv);
    b = fmaf(b, d, ek);
    float sr = __fdividef(1.0f, 1.0f + __expf(-rv));
    return sr * __fdividef(a, b + WKV_EPS);
}

// ---------------- Pass 1: per-chunk affine composition ----------------
// One thread = 4 channels (float4) x 1 chunk. Grid: NB*NC4*NCHUNK threads.
__global__ void __launch_bounds__(256) wkv_pass1(const float4* __restrict__ w,
                                                 const float4* __restrict__ k,
                                                 const float4* __restrict__ v) {
    int tid   = blockIdx.x * 256 + threadIdx.x;
    int c4    = tid & (NC4 - 1);          // low 8 bits: channel/4 (coalesced)
    int chunk = (tid >> 8) & (NCHUNK - 1);
    int b     = tid >> 15;
    int base  = (b * NT + chunk * CLEN) * NC4 + c4;

    float4 D  = make_float4(1.f, 1.f, 1.f, 1.f);
    float4 A  = make_float4(0.f, 0.f, 0.f, 0.f);
    float4 Bb = make_float4(0.f, 0.f, 0.f, 0.f);

#pragma unroll 8
    for (int t = 0; t < CLEN; t++) {
        float4 wv = w[base + t * NC4];
        float4 kv = k[base + t * NC4];
        float4 vv = v[base + t * NC4];
        wkv_acc(wv.x, kv.x, vv.x, A.x, Bb.x, D.x);
        wkv_acc(wv.y, kv.y, vv.y, A.y, Bb.y, D.y);
        wkv_acc(wv.z, kv.z, vv.z, A.z, Bb.z, D.z);
        wkv_acc(wv.w, kv.w, vv.w, A.w, Bb.w, D.w);
    }

    int s = (chunk * NB + b) * NC4 + c4;
    reinterpret_cast<float4*>(g_D)[s] = D;
    reinterpret_cast<float4*>(g_A)[s] = A;
    reinterpret_cast<float4*>(g_B)[s] = Bb;
}

// ---------------- Pass 2: exclusive scan over chunk summaries ----------------
// One thread per channel (NB*NC = 8192). Scratch is L2-resident (12 MiB).
__global__ void __launch_bounds__(256) wkv_pass2() {
    int tid = blockIdx.x * 256 + threadIdx.x;
    int c   = tid & (NC - 1);
    int b   = tid >> 10;

    float Ap = 0.f, Bp = 0.f;
#pragma unroll 4
    for (int ch = 0; ch < NCHUNK; ch++) {
        int idx = (ch * NB + b) * NC + c;
        float d  = g_D[idx];
        float a  = g_A[idx];
        float bb = g_B[idx];
        g_A[idx] = Ap;                 // exclusive prefix (state entering chunk)
        g_B[idx] = Bp;
        Ap = fmaf(Ap, d, a);
        Bp = fmaf(Bp, d, bb);
    }
}

// ---------------- Pass 3: re-stream with carry-in, emit output ----------------
__global__ void __launch_bounds__(256) wkv_pass3(const float4* __restrict__ r,
                                                 const float4* __restrict__ w,
                                                 const float4* __restrict__ k,
                                                 const float4* __restrict__ v,
                                                 float4* __restrict__ out) {
    int tid   = blockIdx.x * 256 + threadIdx.x;
    int c4    = tid & (NC4 - 1);
    int chunk = (tid >> 8) & (NCHUNK - 1);
    int b     = tid >> 15;

    int s = (chunk * NB + b) * NC4 + c4;
    float4 A  = reinterpret_cast<const float4*>(g_A)[s];
    float4 Bb = reinterpret_cast<const float4*>(g_B)[s];

    int base = (b * NT + chunk * CLEN) * NC4 + c4;
#pragma unroll 4
    for (int t = 0; t < CLEN; t++) {
        int idx = base + t * NC4;
        float4 rv = r[idx];
        float4 wv = w[idx];
        float4 kv = k[idx];
        float4 vv = v[idx];
        float4 o;
        o.x = wkv_emit(rv.x, wv.x, kv.x, vv.x, A.x, Bb.x);
        o.y = wkv_emit(rv.y, wv.y, kv.y, vv.y, A.y, Bb.y);
        o.z = wkv_emit(rv.z, wv.z, kv.z, vv.z, A.z, Bb.z);
        o.w = wkv_emit(rv.w, wv.w, kv.w, vv.w, A.w, Bb.w);
        out[idx] = o;
    }
}

extern "C" void kernel_launch(void* const* d_in, const int* in_sizes, int n_in,
                              void* d_out, int out_size) {
    const float4* r = (const float4*)d_in[0];
    const float4* w = (const float4*)d_in[1];
    const float4* k = (const float4*)d_in[2];
    const float4* v = (const float4*)d_in[3];
    float4* o = (float4*)d_out;

    const int n13 = NB * NC4 * NCHUNK;   // 262144 threads, 1024 blocks
    wkv_pass1<<<n13 / 256, 256>>>(w, k, v);
    wkv_pass2<<<(NB * NC) / 256, 256>>>();
    wkv_pass3<<<n13 / 256, 256>>>(r, w, k, v, o);
}

// round 3
// speedup vs baseline: 1.0798x; 1.0798x over previous
#include <cuda_runtime.h>

// RWKV WKV: per-channel affine linear recurrence along T.
//   a_t = d_t * a_{t-1} + ek_t * v_t
//   b_t = d_t * b_{t-1} + ek_t
//   out = sigmoid(r) * a / (b + eps),  d = exp(-exp(w)), ek = exp(k)
//
// 3-pass chunked scan, CLEN=16:
//   (1) per-chunk affine composition  (reads w,k,v = 384 MiB)
//   (2) per-channel exclusive scan over 256 chunk summaries (L2-resident)
//   (3) re-stream with carry-in + output (reads r,w,k,v = 512 MiB, writes 128 MiB)

#define NB 8
#define NT 4096
#define NC 1024
#define NC4 (NC / 4)          // 256 float4 lanes per row
#define NCHUNK 256            // chunks along T
#define CLEN (NT / NCHUNK)    // 16 timesteps per chunk
#define WKV_EPS 1e-6f

// Scratch: chunk summaries, layout [chunk][b][c] (coalesced for all passes).
__device__ float g_D[NCHUNK * NB * NC];   // decay product per chunk
__device__ float g_A[NCHUNK * NB * NC];   // numerator aggregate / excl. prefix
__device__ float g_B[NCHUNK * NB * NC];   // denominator aggregate / excl. prefix

__device__ __forceinline__ void wkv_acc(float wv, float kv, float vv,
                                        float& a, float& b, float& D) {
    float d  = __expf(-__expf(wv));
    float ek = __expf(kv);
    a = fmaf(a, d, ek * vv);
    b = fmaf(b, d, ek);
    D *= d;
}

// One divide total: out = a / ((1 + e^-r) * (b + eps))
__device__ __forceinline__ float wkv_emit(float rv, float wv, float kv, float vv,
                                          float& a, float& b) {
    float d  = __expf(-__expf(wv));
    float ek = __expf(kv);
    a = fmaf(a, d, ek * vv);
    b = fmaf(b, d, ek);
    float denom = (1.0f + __expf(-rv)) * (b + WKV_EPS);
    return __fdividef(a, denom);
}

// ---------------- Pass 1: per-chunk affine composition ----------------
// One thread = 4 channels (float4) x 1 chunk. 524288 threads.
__global__ void __launch_bounds__(256) wkv_pass1(const float4* __restrict__ w,
                                                 const float4* __restrict__ k,
                                                 const float4* __restrict__ v) {
    int tid   = blockIdx.x * 256 + threadIdx.x;
    int c4    = tid & (NC4 - 1);             // bits 0..7  (coalesced)
    int chunk = (tid >> 8) & (NCHUNK - 1);   // bits 8..15
    int b     = tid >> 16;
    int base  = (b * NT + chunk * CLEN) * NC4 + c4;

    float4 D  = make_float4(1.f, 1.f, 1.f, 1.f);
    float4 A  = make_float4(0.f, 0.f, 0.f, 0.f);
    float4 Bb = make_float4(0.f, 0.f, 0.f, 0.f);

#pragma unroll 4
    for (int t = 0; t < CLEN; t++) {
        float4 wv = __ldcs(&w[base + t * NC4]);
        float4 kv = __ldcs(&k[base + t * NC4]);
        float4 vv = __ldcs(&v[base + t * NC4]);
        wkv_acc(wv.x, kv.x, vv.x, A.x, Bb.x, D.x);
        wkv_acc(wv.y, kv.y, vv.y, A.y, Bb.y, D.y);
        wkv_acc(wv.z, kv.z, vv.z, A.z, Bb.z, D.z);
        wkv_acc(wv.w, kv.w, vv.w, A.w, Bb.w, D.w);
    }

    int s = (chunk * NB + b) * NC4 + c4;
    reinterpret_cast<float4*>(g_D)[s] = D;
    reinterpret_cast<float4*>(g_A)[s] = A;
    reinterpret_cast<float4*>(g_B)[s] = Bb;
}

// ---------------- Pass 2: exclusive scan over chunk summaries ----------------
// One thread per channel (NB*NC = 8192). Scratch is L2-resident (24 MiB).
__global__ void __launch_bounds__(256) wkv_pass2() {
    int tid = blockIdx.x * 256 + threadIdx.x;
    int c   = tid & (NC - 1);
    int b   = tid >> 10;

    float Ap = 0.f, Bp = 0.f;
#pragma unroll 4
    for (int ch = 0; ch < NCHUNK; ch++) {
        int idx = (ch * NB + b) * NC + c;
        float d  = g_D[idx];
        float a  = g_A[idx];
        float bb = g_B[idx];
        g_A[idx] = Ap;                 // exclusive prefix (state entering chunk)
        g_B[idx] = Bp;
        Ap = fmaf(Ap, d, a);
        Bp = fmaf(Bp, d, bb);
    }
}

// ---------------- Pass 3: re-stream with carry-in, emit output ----------------
__global__ void __launch_bounds__(256) wkv_pass3(const float4* __restrict__ r,
                                                 const float4* __restrict__ w,
                                                 const float4* __restrict__ k,
                                                 const float4* __restrict__ v,
                                                 float4* __restrict__ out) {
    int tid   = blockIdx.x * 256 + threadIdx.x;
    int c4    = tid & (NC4 - 1);
    int chunk = (tid >> 8) & (NCHUNK - 1);
    int b     = tid >> 16;

    int s = (chunk * NB + b) * NC4 + c4;
    float4 A  = reinterpret_cast<const float4*>(g_A)[s];
    float4 Bb = reinterpret_cast<const float4*>(g_B)[s];

    int base = (b * NT + chunk * CLEN) * NC4 + c4;
#pragma unroll 2
    for (int t = 0; t < CLEN; t++) {
        int idx = base + t * NC4;
        float4 rv = __ldcs(&r[idx]);
        float4 wv = __ldcs(&w[idx]);
        float4 kv = __ldcs(&k[idx]);
        float4 vv = __ldcs(&v[idx]);
        float4 o;
        o.x = wkv_emit(rv.x, wv.x, kv.x, vv.x, A.x, Bb.x);
        o.y = wkv_emit(rv.y, wv.y, kv.y, vv.y, A.y, Bb.y);
        o.z = wkv_emit(rv.z, wv.z, kv.z, vv.z, A.z, Bb.z);
        o.w = wkv_emit(rv.w, wv.w, kv.w, vv.w, A.w, Bb.w);
        __stcs(&out[idx], o);
    }
}

extern "C" void kernel_launch(void* const* d_in, const int* in_sizes, int n_in,
                              void* d_out, int out_size) {
    const float4* r = (const float4*)d_in[0];
    const float4* w = (const float4*)d_in[1];
    const float4* k = (const float4*)d_in[2];
    const float4* v = (const float4*)d_in[3];
    float4* o = (float4*)d_out;

    const int n13 = NB * NC4 * NCHUNK;   // 524288 threads, 2048 blocks
    wkv_pass1<<<n13 / 256, 256>>>(w, k, v);
    wkv_pass2<<<(NB * NC) / 256, 256>>>();
    wkv_pass3<<<n13 / 256, 256>>>(r, w, k, v, o);
}